// round 15
// baseline (speedup 1.0000x reference)
#include <cuda_runtime.h>
#include <cstdint>

#define NB    32
#define NT    24
#define SZ    768
#define NS    6
#define SLAB  128
#define NTHR  512
#define NWARP 16
#define RPF4  (SZ / 4)       // 192 float4 per matrix row
#define RPW   48             // rows per warp
#define PRE   8              // register-prefetch rows per warp: j = 0..7
#define SMJ0  8              // smem-prefetch rows per warp: j = 8..11
#define SMJ1  12
#define SMROWS ((SMJ1 - SMJ0) * NWARP)   // 64 global rows (128..191)
#define SMCHUNKS (SMROWS * 32)           // 2048 x 16B = 32KB
#define CPT   (SMCHUNKS / NTHR)          // 4 cp.async per thread

// relu(y_t) carry produced at step t, consumed at step t+1.
__device__ float g_carry[NT][NB][SZ];
// completion counters: g_done[t][b] counts finished slabs of (t,b)
__device__ int g_done[NT][NB];

__global__ void init_flags_kernel() {
    ((int*)g_done)[threadIdx.x] = 0;      // 768 threads = NT*NB
}

__device__ __forceinline__ void cp_async16(uint32_t saddr, const void* gaddr) {
    asm volatile("cp.async.cg.shared.global [%0], [%1], 16;\n"
                 :: "r"(saddr), "l"(gaddr));
}

__global__ void __launch_bounds__(NTHR, 2)   // force regs<=64: 2 blocks/SM co-residency
scan_kernel(const float* __restrict__ inp,
            const float* __restrict__ param,
            float* __restrict__ out)
{
    __shared__ float  s_y[SZ];                       // 3 KB
    __shared__ float  s_red[NWARP][SLAB];            // 8 KB
    __shared__ float4 s_mat[SMROWS * 32];            // 32 KB: rows 128..191 linear

    const int s    = blockIdx.x;          // slab id 0..NS-1
    const int b    = blockIdx.y;          // batch  0..NB-1
    const int tid  = threadIdx.x;
    const int w    = tid >> 5;
    const int lane = tid & 31;
    const int kbase = s * SLAB;

    const uint32_t s_mat_base = (uint32_t)__cvta_generic_to_shared(s_mat);

    // float4 view of this batch's matrices, offset to our column slab.
    const float4* matb = (const float4*)(inp + (size_t)b * NT * SZ * SZ + kbase);
    const float4* pm = matb;              // step-t matrix tile pointer

    // ---- prologue: register prefetch for t=0 (rows j=0..7 per warp) ----
    float4 m[PRE];
    #pragma unroll
    for (int u = 0; u < PRE; ++u)
        m[u] = __ldcs(&pm[(size_t)(w + NWARP * u) * RPF4 + lane]);

    for (int t = 0; t < NT; ++t) {
        // ---- cp.async -> smem: global rows 128..191, 32KB (R5 position) ----
        #pragma unroll
        for (int k = 0; k < CPT; ++k) {
            int c   = tid + NTHR * k;                 // 0..2047
            int row = (SMJ0 * NWARP) + (c >> 5);      // 128 + c/32
            int ln  = c & 31;
            cp_async16(s_mat_base + (uint32_t)c * 16,
                       &pm[(size_t)row * RPF4 + ln]);
        }
        asm volatile("cp.async.commit_group;\n" ::: "memory");

        // ---- wait for batch b's previous step, then load carry into smem ----
        if (t > 0) {
            if (tid == 0) {
                while (atomicAdd(&g_done[t - 1][b], 0) < NS)
                    __nanosleep(32);
                __threadfence();          // acquire
            }
            __syncthreads();
            for (int i = tid; i < SZ; i += NTHR)
                s_y[i] = __ldcg(&g_carry[t - 1][b][i]);   // L2-coherent read
        } else {
            for (int i = tid; i < SZ; i += NTHR)
                s_y[i] = param[i] + 1.0f;
        }
        asm volatile("cp.async.wait_group 0;\n" ::: "memory");
        __syncthreads();

        // ---- compute ----
        float4 acc = make_float4(0.f, 0.f, 0.f, 0.f);
        // (a) register-prefetched rows
        #pragma unroll
        for (int u = 0; u < PRE; ++u) {
            float yv = s_y[w + NWARP * u];
            acc.x = fmaf(yv, m[u].x, acc.x);
            acc.y = fmaf(yv, m[u].y, acc.y);
            acc.z = fmaf(yv, m[u].z, acc.z);
            acc.w = fmaf(yv, m[u].w, acc.w);
        }
        // (b) smem-prefetched rows j=8..11
        #pragma unroll
        for (int j = SMJ0; j < SMJ1; ++j) {
            int row = w + NWARP * j;
            float4 mm = s_mat[(row - SMJ0 * NWARP) * 32 + lane];
            float yv  = s_y[row];
            acc.x = fmaf(yv, mm.x, acc.x);
            acc.y = fmaf(yv, mm.y, acc.y);
            acc.z = fmaf(yv, mm.z, acc.z);
            acc.w = fmaf(yv, mm.w, acc.w);
        }
        // (c) streamed remainder j=12..47
        #pragma unroll
        for (int j = SMJ1; j < RPW; ++j) {
            float4 mm = __ldcs(&pm[(size_t)(w + NWARP * j) * RPF4 + lane]);
            float yv  = s_y[w + NWARP * j];
            acc.x = fmaf(yv, mm.x, acc.x);
            acc.y = fmaf(yv, mm.y, acc.y);
            acc.z = fmaf(yv, mm.z, acc.z);
            acc.w = fmaf(yv, mm.w, acc.w);
        }

        // ---- publish partials; THE ONE CHANGE vs R5: prefetch t+1 rows now,
        //      so the reduction window carries 16KB/block of next-step loads ----
        ((float4*)s_red[w])[lane] = acc;
        if (t < NT - 1) {
            pm += (size_t)SZ * RPF4;      // advance to step t+1 tile
            #pragma unroll
            for (int u = 0; u < PRE; ++u)
                m[u] = __ldcs(&pm[(size_t)(w + NWARP * u) * RPF4 + lane]);
        }
        __syncthreads();

        // ---- cross-warp reduction ----
        if (tid < SLAB) {
            float sum = 0.f;
            #pragma unroll
            for (int ww = 0; ww < NWARP; ++ww) sum += s_red[ww][tid];
            const int k = kbase + tid;
            if (t == NT - 1) {
                out[b * SZ + k] = sum;                    // pre-ReLU final step
            } else {
                g_carry[t][b][k] = fmaxf(sum, 0.f);       // ReLU carry
            }
            __threadfence();              // release: only writers fence
        }
        __syncthreads();                  // all writers fenced before flag
        if (t < NT - 1 && tid == 0) {
            atomicAdd(&g_done[t][b], 1);
        }
    }
}

extern "C" void kernel_launch(void* const* d_in, const int* in_sizes, int n_in,
                              void* d_out, int out_size)
{
    const float* inp   = (const float*)d_in[0];   // [32,24,768,768] f32
    const float* param = (const float*)d_in[1];   // [768] f32
    float* out         = (float*)d_out;           // [32,768] f32

    init_flags_kernel<<<1, NT * NB>>>();
    dim3 grid(NS, NB);
    scan_kernel<<<grid, NTHR>>>(inp, param, out);
}

// round 16
// speedup vs baseline: 1.1630x; 1.1630x over previous
#include <cuda_runtime.h>
#include <cstdint>

#define NB    32
#define NT    24
#define SZ    768
#define NS    6
#define SLAB  128
#define NTHR  512
#define NWARP 16
#define RPW   (SZ / NWARP)   // rows per warp = 48
#define PRE   8              // register-prefetch rows per warp: j = 0..7
#define SMJ0  8              // smem-prefetch rows per warp: j = 8..11
#define SMJ1  12
#define SMROWS ((SMJ1 - SMJ0) * NWARP)   // 64 global rows (128..191)
#define SMCHUNKS (SMROWS * 32)           // 2048 x 16B = 32KB
#define CPT   (SMCHUNKS / NTHR)          // 4 cp.async per thread

// relu(y_t) carry produced at step t, consumed at step t+1.
__device__ float g_carry[NT][NB][SZ];
// completion counters: g_done[t][b] counts finished slabs of (t,b).
// Zero-initialized at module load; self-reset at end of each run (see epilogue).
__device__ int g_done[NT][NB];
// per-batch finish counter (never reset; grows monotonically across replays)
__device__ int g_fin[NB];

__device__ __forceinline__ void cp_async16(uint32_t saddr, const void* gaddr) {
    asm volatile("cp.async.cg.shared.global [%0], [%1], 16;\n"
                 :: "r"(saddr), "l"(gaddr));
}

__global__ void __launch_bounds__(NTHR, 2)   // force regs<=64: 2 blocks/SM co-residency
scan_kernel(const float* __restrict__ inp,
            const float* __restrict__ param,
            float* __restrict__ out)
{
    __shared__ float  s_y[SZ];                       // 3 KB
    __shared__ float  s_red[NWARP][SLAB];            // 8 KB
    __shared__ float4 s_mat[SMROWS * 32];            // 32 KB: rows 128..191 linear

    const int s    = blockIdx.x;          // slab id 0..NS-1
    const int b    = blockIdx.y;          // batch  0..NB-1
    const int tid  = threadIdx.x;
    const int w    = tid >> 5;
    const int lane = tid & 31;
    const int kbase = s * SLAB;

    const uint32_t s_mat_base = (uint32_t)__cvta_generic_to_shared(s_mat);

    for (int t = 0; t < NT; ++t) {
        // Matrix tile for (b, t), this slab. Row i segment = 32 float4 (512B),
        // one float4 per lane, fully coalesced, streamed once.
        const float4* mat =
            (const float4*)(inp + ((size_t)b * NT + t) * SZ * SZ + kbase);

        // ---- PREFETCH ACROSS THE SYNC (no carry dependency) ----
        // (a) registers: rows j=0..7 for this warp
        float4 m[PRE];
        #pragma unroll
        for (int u = 0; u < PRE; ++u)
            m[u] = __ldcs(&mat[(size_t)(w + NWARP * u) * (SZ / 4) + lane]);

        // (b) cp.async -> smem: global rows 128..191 (j=8..11 for every warp),
        //     32KB, zero register cost. Chunk c (16B) = linear offset 16*c.
        #pragma unroll
        for (int k = 0; k < CPT; ++k) {
            int c   = tid + NTHR * k;                 // 0..2047
            int row = (SMJ0 * NWARP) + (c >> 5);      // 128 + c/32
            int ln  = c & 31;
            cp_async16(s_mat_base + (uint32_t)c * 16,
                       &mat[(size_t)row * (SZ / 4) + ln]);
        }
        asm volatile("cp.async.commit_group;\n" ::: "memory");

        // ---- wait for batch b's previous step, then load carry into smem ----
        if (t > 0) {
            if (tid == 0) {
                while (atomicAdd(&g_done[t - 1][b], 0) < NS)
                    __nanosleep(32);
                __threadfence();          // acquire
            }
            __syncthreads();
            for (int i = tid; i < SZ; i += NTHR)
                s_y[i] = __ldcg(&g_carry[t - 1][b][i]);   // L2-coherent read
        } else {
            for (int i = tid; i < SZ; i += NTHR)
                s_y[i] = param[i] + 1.0f;
        }
        asm volatile("cp.async.wait_group 0;\n" ::: "memory");
        __syncthreads();

        // ---- compute ----
        float4 acc = make_float4(0.f, 0.f, 0.f, 0.f);
        // (a) register-prefetched rows
        #pragma unroll
        for (int u = 0; u < PRE; ++u) {
            float yv = s_y[w + NWARP * u];
            acc.x = fmaf(yv, m[u].x, acc.x);
            acc.y = fmaf(yv, m[u].y, acc.y);
            acc.z = fmaf(yv, m[u].z, acc.z);
            acc.w = fmaf(yv, m[u].w, acc.w);
        }
        // (b) smem-prefetched rows j=8..11 (row = w+16j, q = row-128)
        #pragma unroll
        for (int j = SMJ0; j < SMJ1; ++j) {
            int row = w + NWARP * j;
            float4 mm = s_mat[(row - SMJ0 * NWARP) * 32 + lane];
            float yv  = s_y[row];
            acc.x = fmaf(yv, mm.x, acc.x);
            acc.y = fmaf(yv, mm.y, acc.y);
            acc.z = fmaf(yv, mm.z, acc.z);
            acc.w = fmaf(yv, mm.w, acc.w);
        }
        // (c) streamed remainder j=12..47
        #pragma unroll
        for (int j = SMJ1; j < RPW; ++j) {
            float4 mm = __ldcs(&mat[(size_t)(w + NWARP * j) * (SZ / 4) + lane]);
            float yv  = s_y[w + NWARP * j];
            acc.x = fmaf(yv, mm.x, acc.x);
            acc.y = fmaf(yv, mm.y, acc.y);
            acc.z = fmaf(yv, mm.z, acc.z);
            acc.w = fmaf(yv, mm.w, acc.w);
        }

        // ---- cross-warp reduction ----
        ((float4*)s_red[w])[lane] = acc;
        __syncthreads();

        if (tid < SLAB) {
            float sum = 0.f;
            #pragma unroll
            for (int ww = 0; ww < NWARP; ++ww) sum += s_red[ww][tid];
            const int k = kbase + tid;
            if (t == NT - 1) {
                out[b * SZ + k] = sum;                    // pre-ReLU final step
            } else {
                g_carry[t][b][k] = fmaxf(sum, 0.0f);      // ReLU carry
            }
            __threadfence();              // release: only writers fence
        }
        __syncthreads();                  // all writers fenced before flag
        if (t < NT - 1 && tid == 0) {
            atomicAdd(&g_done[t][b], 1);
        }
    }

    // ---- EPILOGUE: self-reset flags for the next graph replay ----
    // All waits in this block are done. The LAST finisher of batch b this run
    // (old % NS == NS-1, deterministic regardless of arrival order) zeroes
    // batch b's flags. Other batches never read g_done[*][b], so this is safe.
    if (tid == 0) {
        int old = atomicAdd(&g_fin[b], 1);
        if ((old % NS) == NS - 1) {
            #pragma unroll
            for (int tt = 0; tt < NT - 1; ++tt)
                g_done[tt][b] = 0;
            __threadfence();
        }
    }
}

extern "C" void kernel_launch(void* const* d_in, const int* in_sizes, int n_in,
                              void* d_out, int out_size)
{
    const float* inp   = (const float*)d_in[0];   // [32,24,768,768] f32
    const float* param = (const float*)d_in[1];   // [768] f32
    float* out         = (float*)d_out;           // [32,768] f32

    dim3 grid(NS, NB);
    scan_kernel<<<grid, NTHR>>>(inp, param, out);
}